// round 7
// baseline (speedup 1.0000x reference)
#include <cuda_runtime.h>
#include <cuda_fp16.h>
#include <cstdint>

// SimpleGNNBlock: out[b,k] = sum_p relu( relu(feats[b,p,:] @ W1 + b1) @ W2 + b2 )
// feats = [dx, dy, 1/sqrt(dx^2+dy^2+1e-6), m_p],  B=32768, P=128, H=64.
//
// R6: zero-smem dataflow between layers. Each warp owns 16 p-rows end-to-end:
// layer-1 m16n8k8 tf32 accumulator fragments ARE (after relu+f16 pack) the
// layer-2 m16n8k16 A fragments -> h never touches shared memory. W2 B-frags
// for all 64 cols register-resident (64 regs); W1 frags from smem per batch;
// b2 scalar; feats computed per-lane (redundant, no smem/shuffle/sync).

#define BATCHES 32768
#define PP 128
#define HH 64
#define GRID 4096
#define BPC (BATCHES / GRID)    // 8

__device__ __forceinline__ uint32_t f2tf32(float x) {
    uint32_t u;
    asm("cvt.rna.tf32.f32 %0, %1;" : "=r"(u) : "f"(x));
    return u;
}
// pack two fp32 -> f16x2 {lo, hi}
__device__ __forceinline__ uint32_t pack_f16(float lo, float hi) {
    uint32_t u;
    asm("cvt.rn.f16x2.f32 %0, %1, %2;" : "=r"(u) : "f"(hi), "f"(lo));
    return u;
}

__global__ __launch_bounds__(256, 2)
void gnn_kernel(const float* __restrict__ planet_xy,   // (B,P,2)
                const float* __restrict__ planet_m,    // (P)
                const float* __restrict__ ast_xy,      // (B,2)
                const float* __restrict__ W1,          // (4,H)
                const float* __restrict__ b1,          // (H)
                const float* __restrict__ W2,          // (H,H) [j][k]
                const float* __restrict__ b2,          // (H)
                float* __restrict__ out)               // (B,H)
{
    __shared__ uint2  w1s[256];   // W1 tf32 frags: [n][lane] -> {b0, b1(bias row)}
    __shared__ float2 b2p[32];    // b2 as pairs
    __shared__ float  sacc[HH];

    const int tid  = threadIdx.x;
    const int lane = tid & 31;
    const int w    = tid >> 5;    // warp 0..7 -> p-rows w*16 .. w*16+15
    const int g    = lane >> 2;   // group 0..7
    const int t    = lane & 3;    // thread-in-group

    // ---- W2 fp16 B-fragments, all 8 n-tiles x 4 k-tiles (64 regs) ----
    // m16n8k16.row.col: b0={B[kt*16+2t][col], B[..+1][col]}, b1={+8,+9 rows}
    uint32_t bf0[8][4], bf1[8][4];
    #pragma unroll
    for (int n = 0; n < 8; ++n) {
        int col = n * 8 + g;
        #pragma unroll
        for (int kt = 0; kt < 4; ++kt) {
            bf0[n][kt] = pack_f16(W2[(kt * 16 + 2 * t)     * HH + col],
                                  W2[(kt * 16 + 2 * t + 1) * HH + col]);
            bf1[n][kt] = pack_f16(W2[(kt * 16 + 2 * t + 8) * HH + col],
                                  W2[(kt * 16 + 2 * t + 9) * HH + col]);
        }
    }

    // ---- W1 tf32 B-frags to smem: entry (n = tid>>5, l = tid&31) ----
    {
        int n = tid >> 5, l = tid & 31;
        int gg = l >> 2, tt = l & 3;
        int col = n * 8 + gg;
        w1s[tid] = make_uint2(f2tf32(W1[tt * HH + col]),
                              (tt == 0) ? f2tf32(b1[col]) : 0u);
    }
    if (tid < 32) b2p[tid] = make_float2(b2[2 * tid], b2[2 * tid + 1]);
    if (tid < HH) sacc[tid] = 0.0f;

    const uint32_t a1pad = (t == 0) ? 0x3f800000u : 0u;  // tf32 1.0 bias col
    // per-lane m constants for own rows
    const uint32_t fm0 = f2tf32(planet_m[w * 16 + g]);
    const uint32_t fm1 = f2tf32(planet_m[w * 16 + g + 8]);

    __syncthreads();

    // prefetch batch 0 inputs
    int b = blockIdx.x;
    float2 pxy0 = reinterpret_cast<const float2*>(planet_xy)[b * PP + w * 16 + g];
    float2 pxy1 = reinterpret_cast<const float2*>(planet_xy)[b * PP + w * 16 + g + 8];
    float2 axy  = reinterpret_cast<const float2*>(ast_xy)[b];

    for (int it = 0; it < BPC; ++it) {
        b = blockIdx.x + it * GRID;

        // ---- feats -> layer-1 A fragments, fully in-lane ----
        float dx0 = pxy0.x - axy.x, dy0 = pxy0.y - axy.y;
        float dx1 = pxy1.x - axy.x, dy1 = pxy1.y - axy.y;
        float inv0 = rsqrtf(fmaf(dx0, dx0, fmaf(dy0, dy0, 1e-6f)));
        float inv1 = rsqrtf(fmaf(dx1, dx1, fmaf(dy1, dy1, 1e-6f)));
        float sel0 = (t == 0) ? dx0 : (t == 1) ? dy0 : inv0;
        float sel1 = (t == 0) ? dx1 : (t == 1) ? dy1 : inv1;
        uint32_t a0 = (t == 3) ? fm0 : f2tf32(sel0);   // A[g][t]
        uint32_t a1 = (t == 3) ? fm1 : f2tf32(sel1);   // A[g+8][t]

        // software-pipeline next batch's loads
        if (it + 1 < BPC) {
            int bn = b + GRID;
            pxy0 = reinterpret_cast<const float2*>(planet_xy)[bn * PP + w * 16 + g];
            pxy1 = reinterpret_cast<const float2*>(planet_xy)[bn * PP + w * 16 + g + 8];
            axy  = reinterpret_cast<const float2*>(ast_xy)[bn];
        }

        // ---- layer 1: 8 MMAs -> h fragments stay in registers ----
        uint32_t hf0[8], hf1[8];
        #pragma unroll
        for (int n = 0; n < 8; ++n) {
            uint2 wf = w1s[n * 32 + lane];
            float c0 = 0.f, c1 = 0.f, c2 = 0.f, c3 = 0.f;
            asm volatile(
                "mma.sync.aligned.m16n8k8.row.col.f32.tf32.tf32.f32 "
                "{%0,%1,%2,%3}, {%4,%5,%6,%7}, {%8,%9}, {%0,%1,%2,%3};"
                : "+f"(c0), "+f"(c1), "+f"(c2), "+f"(c3)
                : "r"(a0), "r"(a1), "r"(a1pad), "r"(a1pad),
                  "r"(wf.x), "r"(wf.y));
            hf0[n] = pack_f16(fmaxf(c0, 0.f), fmaxf(c1, 0.f));  // = A2[g][n*8+2t..]
            hf1[n] = pack_f16(fmaxf(c2, 0.f), fmaxf(c3, 0.f));  // = A2[g+8][..]
        }

        // ---- layer 2 in two n-halves (keeps accumulators at 16 regs) ----
        #pragma unroll
        for (int nh = 0; nh < 2; ++nh) {
            float c[4][4];
            #pragma unroll
            for (int nn = 0; nn < 4; ++nn) {
                c[nn][0] = 0.f; c[nn][1] = 0.f; c[nn][2] = 0.f; c[nn][3] = 0.f;
            }
            #pragma unroll
            for (int kt = 0; kt < 4; ++kt) {
                uint32_t A0 = hf0[2 * kt];
                uint32_t A1 = hf1[2 * kt];
                uint32_t A2 = hf0[2 * kt + 1];
                uint32_t A3 = hf1[2 * kt + 1];
                #pragma unroll
                for (int nn = 0; nn < 4; ++nn) {
                    int n = nh * 4 + nn;
                    asm volatile(
                        "mma.sync.aligned.m16n8k16.row.col.f32.f16.f16.f32 "
                        "{%0,%1,%2,%3}, {%4,%5,%6,%7}, {%8,%9}, {%0,%1,%2,%3};"
                        : "+f"(c[nn][0]), "+f"(c[nn][1]), "+f"(c[nn][2]), "+f"(c[nn][3])
                        : "r"(A0), "r"(A1), "r"(A2), "r"(A3),
                          "r"(bf0[n][kt]), "r"(bf1[n][kt]));
                }
            }
            // bias + relu + row-pair sum + g-reduction + cross-warp atomics
            #pragma unroll
            for (int nn = 0; nn < 4; ++nn) {
                int n = nh * 4 + nn;
                float2 bb = b2p[n * 4 + t];          // {b2[col0], b2[col0+1]}
                float v0 = fmaxf(c[nn][0] + bb.x, 0.f) + fmaxf(c[nn][2] + bb.x, 0.f);
                float v1 = fmaxf(c[nn][1] + bb.y, 0.f) + fmaxf(c[nn][3] + bb.y, 0.f);
                v0 += __shfl_xor_sync(0xffffffffu, v0, 4);
                v1 += __shfl_xor_sync(0xffffffffu, v1, 4);
                v0 += __shfl_xor_sync(0xffffffffu, v0, 8);
                v1 += __shfl_xor_sync(0xffffffffu, v1, 8);
                v0 += __shfl_xor_sync(0xffffffffu, v0, 16);
                v1 += __shfl_xor_sync(0xffffffffu, v1, 16);
                if (lane < 4) {                      // g == 0
                    int col0 = n * 8 + 2 * t;
                    atomicAdd(&sacc[col0],     v0);
                    atomicAdd(&sacc[col0 + 1], v1);
                }
            }
        }

        __syncthreads();
        if (tid < HH) {
            out[b * HH + tid] = sacc[tid];
            sacc[tid] = 0.0f;
        }
        __syncthreads();
    }
}

extern "C" void kernel_launch(void* const* d_in, const int* in_sizes, int n_in,
                              void* d_out, int out_size) {
    (void)in_sizes; (void)n_in; (void)out_size;
    const float* planet_xy = (const float*)d_in[0];
    const float* planet_m  = (const float*)d_in[1];
    const float* ast_xy    = (const float*)d_in[2];
    const float* W1        = (const float*)d_in[3];
    const float* b1        = (const float*)d_in[4];
    const float* W2        = (const float*)d_in[5];
    const float* b2        = (const float*)d_in[6];
    float* out             = (float*)d_out;

    gnn_kernel<<<GRID, 256>>>(planet_xy, planet_m, ast_xy, W1, b1, W2, b2, out);
}

// round 9
// speedup vs baseline: 1.2450x; 1.2450x over previous
#include <cuda_runtime.h>
#include <cuda_fp16.h>
#include <cstdint>

// SimpleGNNBlock: out[b,k] = sum_p relu( relu(feats[b,p,:] @ W1 + b1) @ W2 + b2 )
// feats = [dx, dy, 1/sqrt(dx^2+dy^2+1e-6), m_p],  B=32768, P=128, H=64.
//
// R8: fused register dataflow (layer-1 accum frag == layer-2 A frag, h never
// in smem) with column-split warps to stay under the register ceiling:
// warp w owns rows (w>>1)*32..+31 and cols (w&1)*32..+31. Layer 1 duplicated
// across the column pair (cheap tf32 k=8 MMAs), W2 B-frags only 32 regs.
// Zero smem traffic in the main loop.

#define BATCHES 32768
#define PP 128
#define HH 64
#define GRID 4096
#define BPC (BATCHES / GRID)    // 8

__device__ __forceinline__ uint32_t f2tf32(float x) {
    uint32_t u;
    asm("cvt.rna.tf32.f32 %0, %1;" : "=r"(u) : "f"(x));
    return u;
}
// pack two fp32 -> f16x2 {lo, hi}
__device__ __forceinline__ uint32_t pack_f16(float lo, float hi) {
    uint32_t u;
    asm("cvt.rn.f16x2.f32 %0, %1, %2;" : "=r"(u) : "f"(hi), "f"(lo));
    return u;
}

__global__ __launch_bounds__(256, 2)
void gnn_kernel(const float* __restrict__ planet_xy,   // (B,P,2)
                const float* __restrict__ planet_m,    // (P)
                const float* __restrict__ ast_xy,      // (B,2)
                const float* __restrict__ W1,          // (4,H)
                const float* __restrict__ b1,          // (H)
                const float* __restrict__ W2,          // (H,H) [j][k]
                const float* __restrict__ b2,          // (H)
                float* __restrict__ out)               // (B,H)
{
    __shared__ float sacc[HH];

    const int tid  = threadIdx.x;
    const int lane = tid & 31;
    const int w    = tid >> 5;    // warp 0..7
    const int g    = lane >> 2;   // group 0..7
    const int t    = lane & 3;    // thread-in-group
    const int mg   = w >> 1;      // row-block 0..3: rows mg*32 .. +31
    const int ch   = w & 1;       // col-half 0..1:  cols ch*32 .. +31

    // ---- W2 fp16 B-fragments for this warp's 4 n-tiles (32 regs) ----
    // m16n8k16.row.col: bf0={B[kt*16+2t][col],B[+1][col]}, bf1={rows +8,+9}
    uint32_t bf0[4][4], bf1[4][4];
    float2 bb[4];                 // b2 pair per n-tile
    #pragma unroll
    for (int nt = 0; nt < 4; ++nt) {
        int col = ch * 32 + nt * 8 + g;
        #pragma unroll
        for (int kt = 0; kt < 4; ++kt) {
            bf0[nt][kt] = pack_f16(W2[(kt * 16 + 2 * t)     * HH + col],
                                   W2[(kt * 16 + 2 * t + 1) * HH + col]);
            bf1[nt][kt] = pack_f16(W2[(kt * 16 + 2 * t + 8) * HH + col],
                                   W2[(kt * 16 + 2 * t + 9) * HH + col]);
        }
        int c0 = ch * 32 + nt * 8 + 2 * t;
        bb[nt] = make_float2(b2[c0], b2[c0 + 1]);
    }

    // ---- W1 tf32 B-fragments, register-resident (16 regs) ----
    // m16n8k8.row.col: w1x = B[t][col] = W1[t][col]; w1y = bias row (t==0).
    uint32_t w1x[8], w1y[8];
    #pragma unroll
    for (int n = 0; n < 8; ++n) {
        int col = n * 8 + g;
        w1x[n] = f2tf32(W1[t * HH + col]);
        w1y[n] = (t == 0) ? f2tf32(b1[col]) : 0u;
    }
    const uint32_t a1pad = (t == 0) ? 0x3f800000u : 0u;  // tf32 1.0 bias col

    // per-lane planet masses for this warp's 4 row positions
    uint32_t fm[4];
    #pragma unroll
    for (int mt = 0; mt < 2; ++mt) {
        fm[2 * mt]     = f2tf32(planet_m[mg * 32 + mt * 16 + g]);
        fm[2 * mt + 1] = f2tf32(planet_m[mg * 32 + mt * 16 + g + 8]);
    }

    if (tid < HH) sacc[tid] = 0.0f;
    __syncthreads();

    // prefetch batch 0 inputs
    int b = blockIdx.x;
    float2 pxy[4], axy;
    #pragma unroll
    for (int mt = 0; mt < 2; ++mt) {
        pxy[2 * mt]     = reinterpret_cast<const float2*>(planet_xy)[b * PP + mg * 32 + mt * 16 + g];
        pxy[2 * mt + 1] = reinterpret_cast<const float2*>(planet_xy)[b * PP + mg * 32 + mt * 16 + g + 8];
    }
    axy = reinterpret_cast<const float2*>(ast_xy)[b];

    for (int it = 0; it < BPC; ++it) {
        b = blockIdx.x + it * GRID;

        // ---- feats -> layer-1 A fragments (per-lane, no smem) ----
        uint32_t a[4];
        #pragma unroll
        for (int r = 0; r < 4; ++r) {
            float dx = pxy[r].x - axy.x;
            float dy = pxy[r].y - axy.y;
            float inv = rsqrtf(fmaf(dx, dx, fmaf(dy, dy, 1e-6f)));
            float sel = (t == 0) ? dx : (t == 1) ? dy : inv;
            a[r] = (t == 3) ? fm[r] : f2tf32(sel);
        }

        // software-pipeline next batch's loads
        if (it + 1 < BPC) {
            int bn = b + GRID;
            #pragma unroll
            for (int mt = 0; mt < 2; ++mt) {
                pxy[2 * mt]     = reinterpret_cast<const float2*>(planet_xy)[bn * PP + mg * 32 + mt * 16 + g];
                pxy[2 * mt + 1] = reinterpret_cast<const float2*>(planet_xy)[bn * PP + mg * 32 + mt * 16 + g + 8];
            }
            axy = reinterpret_cast<const float2*>(ast_xy)[bn];
        }

        float s0[4] = {0.f, 0.f, 0.f, 0.f};
        float s1[4] = {0.f, 0.f, 0.f, 0.f};

        #pragma unroll
        for (int mt = 0; mt < 2; ++mt) {
            // ---- layer 1: 8 tf32 MMAs -> h frags in registers ----
            uint32_t hf0[8], hf1[8];
            #pragma unroll
            for (int n = 0; n < 8; ++n) {
                float c0 = 0.f, c1 = 0.f, c2 = 0.f, c3 = 0.f;
                asm volatile(
                    "mma.sync.aligned.m16n8k8.row.col.f32.tf32.tf32.f32 "
                    "{%0,%1,%2,%3}, {%4,%5,%6,%7}, {%8,%9}, {%0,%1,%2,%3};"
                    : "+f"(c0), "+f"(c1), "+f"(c2), "+f"(c3)
                    : "r"(a[2 * mt]), "r"(a[2 * mt + 1]), "r"(a1pad), "r"(a1pad),
                      "r"(w1x[n]), "r"(w1y[n]));
                hf0[n] = pack_f16(fmaxf(c0, 0.f), fmaxf(c1, 0.f));  // rows g / cols n*8+2t..
                hf1[n] = pack_f16(fmaxf(c2, 0.f), fmaxf(c3, 0.f));  // rows g+8
            }

            // ---- layer 2: 16 f16 MMAs over this warp's 4 n-tiles ----
            float c[4][4];
            #pragma unroll
            for (int nt = 0; nt < 4; ++nt) {
                c[nt][0] = 0.f; c[nt][1] = 0.f; c[nt][2] = 0.f; c[nt][3] = 0.f;
            }
            #pragma unroll
            for (int kt = 0; kt < 4; ++kt) {
                uint32_t A0 = hf0[2 * kt];
                uint32_t A1 = hf1[2 * kt];
                uint32_t A2 = hf0[2 * kt + 1];
                uint32_t A3 = hf1[2 * kt + 1];
                #pragma unroll
                for (int nt = 0; nt < 4; ++nt) {
                    asm volatile(
                        "mma.sync.aligned.m16n8k16.row.col.f32.f16.f16.f32 "
                        "{%0,%1,%2,%3}, {%4,%5,%6,%7}, {%8,%9}, {%0,%1,%2,%3};"
                        : "+f"(c[nt][0]), "+f"(c[nt][1]), "+f"(c[nt][2]), "+f"(c[nt][3])
                        : "r"(A0), "r"(A1), "r"(A2), "r"(A3),
                          "r"(bf0[nt][kt]), "r"(bf1[nt][kt]));
                }
            }

            // bias + relu + fold rows into per-batch partials
            #pragma unroll
            for (int nt = 0; nt < 4; ++nt) {
                s0[nt] += fmaxf(c[nt][0] + bb[nt].x, 0.f) + fmaxf(c[nt][2] + bb[nt].x, 0.f);
                s1[nt] += fmaxf(c[nt][1] + bb[nt].y, 0.f) + fmaxf(c[nt][3] + bb[nt].y, 0.f);
            }
        }

        // ---- reduce over g (shuffles), then cross-warp smem atomics ----
        #pragma unroll
        for (int nt = 0; nt < 4; ++nt) {
            float v0 = s0[nt], v1 = s1[nt];
            v0 += __shfl_xor_sync(0xffffffffu, v0, 4);
            v1 += __shfl_xor_sync(0xffffffffu, v1, 4);
            v0 += __shfl_xor_sync(0xffffffffu, v0, 8);
            v1 += __shfl_xor_sync(0xffffffffu, v1, 8);
            v0 += __shfl_xor_sync(0xffffffffu, v0, 16);
            v1 += __shfl_xor_sync(0xffffffffu, v1, 16);
            if (lane < 4) {                       // g == 0
                int col0 = ch * 32 + nt * 8 + 2 * t;
                atomicAdd(&sacc[col0],     v0);
                atomicAdd(&sacc[col0 + 1], v1);
            }
        }

        __syncthreads();
        if (tid < HH) {
            out[b * HH + tid] = sacc[tid];
            sacc[tid] = 0.0f;
        }
        __syncthreads();
    }
}

extern "C" void kernel_launch(void* const* d_in, const int* in_sizes, int n_in,
                              void* d_out, int out_size) {
    (void)in_sizes; (void)n_in; (void)out_size;
    const float* planet_xy = (const float*)d_in[0];
    const float* planet_m  = (const float*)d_in[1];
    const float* ast_xy    = (const float*)d_in[2];
    const float* W1        = (const float*)d_in[3];
    const float* b1        = (const float*)d_in[4];
    const float* W2        = (const float*)d_in[5];
    const float* b2        = (const float*)d_in[6];
    float* out             = (float*)d_out;

    gnn_kernel<<<GRID, 256>>>(planet_xy, planet_m, ast_xy, W1, b1, W2, b2, out);
}

// round 10
// speedup vs baseline: 1.3924x; 1.1184x over previous
#include <cuda_runtime.h>
#include <cuda_fp16.h>
#include <cstdint>

// SimpleGNNBlock: out[b,k] = sum_p relu( relu(feats[b,p,:] @ W1 + b1) @ W2 + b2 )
// feats = [dx, dy, 1/sqrt(dx^2+dy^2+1e-6), m_p],  B=32768, P=128, H=64.
//
// R10: R5 dataflow (layer1 MMA -> h fp16 in smem -> layer2 MMA) with the
// layer-2 warp tile at 32 rows x 32 cols: h read replication drops 4x -> 2x
// (crossbar traffic ~-40%), W2 B-frags are 32 regs (no spill), bias-MMAs
// replaced by scalar adds. feats computed per-lane, no feats smem.

#define BATCHES 32768
#define PP 128
#define HH 64
#define GRID 4096
#define BPC (BATCHES / GRID)    // 8
#define HW 36                   // h row stride in words; 36%32==4 -> conflict-free

__device__ __forceinline__ uint32_t f2tf32(float x) {
    uint32_t u;
    asm("cvt.rna.tf32.f32 %0, %1;" : "=r"(u) : "f"(x));
    return u;
}
// pack two fp32 -> f16x2 {lo, hi}
__device__ __forceinline__ uint32_t pack_f16(float lo, float hi) {
    uint32_t u;
    asm("cvt.rn.f16x2.f32 %0, %1, %2;" : "=r"(u) : "f"(hi), "f"(lo));
    return u;
}

__global__ __launch_bounds__(256, 2)
void gnn_kernel(const float* __restrict__ planet_xy,   // (B,P,2)
                const float* __restrict__ planet_m,    // (P)
                const float* __restrict__ ast_xy,      // (B,2)
                const float* __restrict__ W1,          // (4,H)
                const float* __restrict__ b1,          // (H)
                const float* __restrict__ W2,          // (H,H) [j][k]
                const float* __restrict__ b2,          // (H)
                float* __restrict__ out)               // (B,H)
{
    __shared__ uint32_t h2[128 * HW];   // h as fp16x2 pairs, stride HW words
    __shared__ float    sacc[HH];

    const int tid  = threadIdx.x;
    const int lane = tid & 31;
    const int w    = tid >> 5;    // warp 0..7
    const int g    = lane >> 2;   // group 0..7
    const int t    = lane & 3;    // thread-in-group
    const int mg   = w >> 1;      // layer-2 row block: rows mg*32 .. +31
    const int ch   = w & 1;       // layer-2 col half:  cols ch*32 .. +31

    // ---- W2 fp16 B-fragments for this warp's 4 n-tiles (32 regs) ----
    uint32_t bf0[4][4], bf1[4][4];
    float2 bb[4];
    #pragma unroll
    for (int nt = 0; nt < 4; ++nt) {
        int col = ch * 32 + nt * 8 + g;
        #pragma unroll
        for (int kt = 0; kt < 4; ++kt) {
            bf0[nt][kt] = pack_f16(W2[(kt * 16 + 2 * t)     * HH + col],
                                   W2[(kt * 16 + 2 * t + 1) * HH + col]);
            bf1[nt][kt] = pack_f16(W2[(kt * 16 + 2 * t + 8) * HH + col],
                                   W2[(kt * 16 + 2 * t + 9) * HH + col]);
        }
        int c0 = ch * 32 + nt * 8 + 2 * t;
        bb[nt] = make_float2(b2[c0], b2[c0 + 1]);
    }

    // ---- W1 tf32 B-fragments (16 regs) ----
    uint32_t w1x[8], w1y[8];
    #pragma unroll
    for (int n = 0; n < 8; ++n) {
        int col = n * 8 + g;
        w1x[n] = f2tf32(W1[t * HH + col]);
        w1y[n] = (t == 0) ? f2tf32(b1[col]) : 0u;
    }
    const uint32_t a1pad = (t == 0) ? 0x3f800000u : 0u;  // tf32 1.0 (bias col)

    // per-lane masses for layer-1 rows (w*16+g, w*16+g+8)
    const uint32_t fm0 = f2tf32(planet_m[w * 16 + g]);
    const uint32_t fm1 = f2tf32(planet_m[w * 16 + g + 8]);

    if (tid < HH) sacc[tid] = 0.0f;
    __syncthreads();

    // prefetch batch 0 inputs
    int b = blockIdx.x;
    float2 pxy0 = reinterpret_cast<const float2*>(planet_xy)[b * PP + w * 16 + g];
    float2 pxy1 = reinterpret_cast<const float2*>(planet_xy)[b * PP + w * 16 + g + 8];
    float2 axy  = reinterpret_cast<const float2*>(ast_xy)[b];

    for (int it = 0; it < BPC; ++it) {
        b = blockIdx.x + it * GRID;

        // ---- feats -> layer-1 A fragments (per-lane) ----
        float dx0 = pxy0.x - axy.x, dy0 = pxy0.y - axy.y;
        float dx1 = pxy1.x - axy.x, dy1 = pxy1.y - axy.y;
        float inv0 = rsqrtf(fmaf(dx0, dx0, fmaf(dy0, dy0, 1e-6f)));
        float inv1 = rsqrtf(fmaf(dx1, dx1, fmaf(dy1, dy1, 1e-6f)));
        float sel0 = (t == 0) ? dx0 : (t == 1) ? dy0 : inv0;
        float sel1 = (t == 0) ? dx1 : (t == 1) ? dy1 : inv1;
        uint32_t a0 = (t == 3) ? fm0 : f2tf32(sel0);
        uint32_t a1 = (t == 3) ? fm1 : f2tf32(sel1);

        // software-pipeline next batch's loads
        if (it + 1 < BPC) {
            int bn = b + GRID;
            pxy0 = reinterpret_cast<const float2*>(planet_xy)[bn * PP + w * 16 + g];
            pxy1 = reinterpret_cast<const float2*>(planet_xy)[bn * PP + w * 16 + g + 8];
            axy  = reinterpret_cast<const float2*>(ast_xy)[bn];
        }

        // ---- layer 1: warp w owns rows w*16..+15, all 8 n-tiles ----
        #pragma unroll
        for (int n = 0; n < 8; ++n) {
            float c0 = 0.f, c1 = 0.f, c2 = 0.f, c3 = 0.f;
            asm volatile(
                "mma.sync.aligned.m16n8k8.row.col.f32.tf32.tf32.f32 "
                "{%0,%1,%2,%3}, {%4,%5,%6,%7}, {%8,%9}, {%0,%1,%2,%3};"
                : "+f"(c0), "+f"(c1), "+f"(c2), "+f"(c3)
                : "r"(a0), "r"(a1), "r"(a1pad), "r"(a1pad),
                  "r"(w1x[n]), "r"(w1y[n]));
            // h frag (row, cols n*8+2t,+1) -> fp16x2 word (n*4+t) of row
            h2[(w * 16 + g)     * HW + n * 4 + t] = pack_f16(fmaxf(c0, 0.f), fmaxf(c1, 0.f));
            h2[(w * 16 + g + 8) * HW + n * 4 + t] = pack_f16(fmaxf(c2, 0.f), fmaxf(c3, 0.f));
        }
        __syncthreads();   // h2 complete; also fences prev-iter sacc store

        // ---- layer 2: rows mg*32..+31 (2 m-tiles) x cols ch*32..+31 ----
        float s0[4] = {0.f, 0.f, 0.f, 0.f};
        float s1[4] = {0.f, 0.f, 0.f, 0.f};
        #pragma unroll
        for (int mt = 0; mt < 2; ++mt) {
            const int r0 = mg * 32 + mt * 16 + g;
            float c[4][4];
            #pragma unroll
            for (int nt = 0; nt < 4; ++nt) {
                c[nt][0] = 0.f; c[nt][1] = 0.f; c[nt][2] = 0.f; c[nt][3] = 0.f;
            }
            #pragma unroll
            for (int kt = 0; kt < 4; ++kt) {
                uint32_t A0 = h2[r0       * HW + kt * 8 + t];
                uint32_t A1 = h2[(r0 + 8) * HW + kt * 8 + t];
                uint32_t A2 = h2[r0       * HW + kt * 8 + t + 4];
                uint32_t A3 = h2[(r0 + 8) * HW + kt * 8 + t + 4];
                #pragma unroll
                for (int nt = 0; nt < 4; ++nt) {
                    asm volatile(
                        "mma.sync.aligned.m16n8k16.row.col.f32.f16.f16.f32 "
                        "{%0,%1,%2,%3}, {%4,%5,%6,%7}, {%8,%9}, {%0,%1,%2,%3};"
                        : "+f"(c[nt][0]), "+f"(c[nt][1]), "+f"(c[nt][2]), "+f"(c[nt][3])
                        : "r"(A0), "r"(A1), "r"(A2), "r"(A3),
                          "r"(bf0[nt][kt]), "r"(bf1[nt][kt]));
                }
            }
            #pragma unroll
            for (int nt = 0; nt < 4; ++nt) {
                s0[nt] += fmaxf(c[nt][0] + bb[nt].x, 0.f) + fmaxf(c[nt][2] + bb[nt].x, 0.f);
                s1[nt] += fmaxf(c[nt][1] + bb[nt].y, 0.f) + fmaxf(c[nt][3] + bb[nt].y, 0.f);
            }
        }

        // ---- reduce over g (shuffles), cross-warp smem atomics ----
        #pragma unroll
        for (int nt = 0; nt < 4; ++nt) {
            float v0 = s0[nt], v1 = s1[nt];
            v0 += __shfl_xor_sync(0xffffffffu, v0, 4);
            v1 += __shfl_xor_sync(0xffffffffu, v1, 4);
            v0 += __shfl_xor_sync(0xffffffffu, v0, 8);
            v1 += __shfl_xor_sync(0xffffffffu, v1, 8);
            v0 += __shfl_xor_sync(0xffffffffu, v0, 16);
            v1 += __shfl_xor_sync(0xffffffffu, v1, 16);
            if (lane < 4) {                       // g == 0
                int col0 = ch * 32 + nt * 8 + 2 * t;
                atomicAdd(&sacc[col0],     v0);
                atomicAdd(&sacc[col0 + 1], v1);
            }
        }

        __syncthreads();   // atomics done; h2 reads done (safe to rewrite next iter)
        if (tid < HH) {
            out[b * HH + tid] = sacc[tid];
            sacc[tid] = 0.0f;
        }
        // next-iter layer-1 sync orders this store before new atomics
    }
}

extern "C" void kernel_launch(void* const* d_in, const int* in_sizes, int n_in,
                              void* d_out, int out_size) {
    (void)in_sizes; (void)n_in; (void)out_size;
    const float* planet_xy = (const float*)d_in[0];
    const float* planet_m  = (const float*)d_in[1];
    const float* ast_xy    = (const float*)d_in[2];
    const float* W1        = (const float*)d_in[3];
    const float* b1        = (const float*)d_in[4];
    const float* W2        = (const float*)d_in[5];
    const float* b2        = (const float*)d_in[6];
    float* out             = (float*)d_out;

    gnn_kernel<<<GRID, 256>>>(planet_xy, planet_m, ast_xy, W1, b1, W2, b2, out);
}